// round 15
// baseline (speedup 1.0000x reference)
#include <cuda_runtime.h>

// DynamicUpsamplingFilter — R12 champion + TILE_H=2: the depth-2 rolling
// filter pipeline runs continuously across 10 kernel-rows (2 output rows),
// halving per-CTA pipeline-drain / barrier / fill overhead.
//   x:       (4, 3, 180, 320) f32
//   filters: (4, 25, 16, 180, 320) f32
//   out:     (4, 48, 180, 320) f32
//   out[n, c*16+u, h, w] = sum_p x_pad[n, c, h+p/5-2, w+p%5-2] * filters[n, p, u, h, w]

#define NN 4
#define CC 3
#define HH 180
#define WW 320
#define UU 16
#define KH 5
#define KW 5
#define PP (KH*KW)
#define TILE_W 64
#define TILE_H 2
#define SROWS 6                  // KH + TILE_H - 1 patch rows
#define SROW 68                  // TILE_W + 4 halo
#define XELEMS (CC * SROWS * SROW) // 1224 smem elements

__global__ void __launch_bounds__(256, 4)
duf_kernel(const float* __restrict__ x,
           const float* __restrict__ filters,
           float* __restrict__ out) {
    // Block: (n, 2 h-rows, w-tile of 64). 256 threads = 16 u x 16 w-quads.
    __shared__ float sx[CC][SROWS][SROW];  // 4896 B

    const int wq = threadIdx.x & 15;
    const int u  = threadIdx.x >> 4;
    const int wb = blockIdx.x * TILE_W;
    const int h0 = blockIdx.y * TILE_H;
    const int n  = blockIdx.z;

    const int w0 = wb + wq * 4;
    const float* fp = filters + ((((size_t)n * PP) * UU + u) * HH + h0) * WW + w0;
    const size_t PS = (size_t)UU * HH * WW;  // p-plane stride (elements)
    // filter tap address for global row G (0..9): hh=G/5, i=G%5
    //   fp + hh*WW + (i*KW+j)*PS

    // ---- (1) x-tile loads FIRST (L2 hits ahead of filter DRAM misses in
    //      the L1tex FIFO -> barrier releases on x latency)
    float xv[5];
    #pragma unroll
    for (int k = 0; k < 5; ++k) {
        const int e = threadIdx.x + k * 256;
        float v = 0.0f;
        if (e < XELEMS) {
            const int pos = e % SROW;
            const int t   = e / SROW;
            const int r   = t % SROWS;       // patch row 0..5
            const int c   = t / SROWS;
            const int col = wb + pos - 2;
            const int row = h0 + r - 2;
            if ((unsigned)col < WW && (unsigned)row < HH)
                v = x[((n * CC + c) * HH + row) * WW + col];
        }
        xv[k] = v;
    }

    // ---- (2) hoist filter rows G=0,1: 10 LDG.128 in flight during fill
    float4 cur[KW], nxt[KW];
    #pragma unroll
    for (int j = 0; j < KW; ++j)
        cur[j] = __ldcs(reinterpret_cast<const float4*>(fp + (size_t)j * PS));
    #pragma unroll
    for (int j = 0; j < KW; ++j)
        nxt[j] = __ldcs(reinterpret_cast<const float4*>(fp + (size_t)(KW + j) * PS));

    // ---- (3) store x tile + barrier (waits only on the x loads)
    float* sflat = &sx[0][0][0];
    #pragma unroll
    for (int k = 0; k < 5; ++k) {
        const int e = threadIdx.x + k * 256;
        if (e < XELEMS) sflat[e] = xv[k];
    }
    __syncthreads();

    // ---- (4) 10-row continuous pipeline over 2 output rows ----
    #pragma unroll
    for (int hh = 0; hh < TILE_H; ++hh) {
        float4 acc[CC];
        #pragma unroll
        for (int c = 0; c < CC; ++c) acc[c] = make_float4(0.f, 0.f, 0.f, 0.f);

        #pragma unroll
        for (int i = 0; i < KH; ++i) {
            const int G = hh * KH + i;          // global row 0..9
            #pragma unroll
            for (int c = 0; c < CC; ++c) {
                const float4 a = *reinterpret_cast<const float4*>(&sx[c][hh + i][wq * 4]);
                const float4 b = *reinterpret_cast<const float4*>(&sx[c][hh + i][wq * 4 + 4]);
                const float pr[8] = {a.x, a.y, a.z, a.w, b.x, b.y, b.z, b.w};
                #pragma unroll
                for (int j = 0; j < KW; ++j) {
                    acc[c].x = fmaf(pr[j + 0], cur[j].x, acc[c].x);
                    acc[c].y = fmaf(pr[j + 1], cur[j].y, acc[c].y);
                    acc[c].z = fmaf(pr[j + 2], cur[j].z, acc[c].z);
                    acc[c].w = fmaf(pr[j + 3], cur[j].w, acc[c].w);
                    // after the LAST channel consumes cur[j]: rotate, refill
                    // slot j with global row G+2 (crosses the h boundary)
                    if (c == CC - 1 && G < 2 * KH - 1) {
                        cur[j] = nxt[j];
                        const int G2 = G + 2;
                        if (G2 <= 2 * KH - 1) {
                            const int h2 = G2 / KH, i2 = G2 % KH;
                            nxt[j] = __ldcs(reinterpret_cast<const float4*>(
                                fp + h2 * WW + (size_t)(i2 * KW + j) * PS));
                        }
                    }
                }
            }
        }

        // ---- store row h0+hh: out[n, c*16+u, h0+hh, w0..w0+3] ----
        #pragma unroll
        for (int c = 0; c < CC; ++c) {
            float4* optr = reinterpret_cast<float4*>(
                out + ((((size_t)n * (CC * UU)) + c * UU + u) * HH + h0 + hh) * WW + w0);
            __stcs(optr, acc[c]);
        }
    }
}

extern "C" void kernel_launch(void* const* d_in, const int* in_sizes, int n_in,
                              void* d_out, int out_size) {
    const float* x       = (const float*)d_in[0];
    const float* filters = (const float*)d_in[1];
    float* out           = (float*)d_out;

    dim3 grid(WW / TILE_W, HH / TILE_H, NN);  // (5, 90, 4) = 1800 blocks
    dim3 block(256);
    duf_kernel<<<grid, block>>>(x, filters, out);
}

// round 16
// speedup vs baseline: 1.7840x; 1.7840x over previous
#include <cuda_runtime.h>

// DynamicUpsamplingFilter — converged champion (R12):
//  * x-tile loads issued FIRST: their L2 hits sit ahead of the filter DRAM
//    misses in the per-SM L1tex FIFO, so __syncthreads releases on x latency
//    rather than DRAM latency (R8 finding, -4us).
//  * filter rows 0+1 hoisted: 10 LDG.128 in flight through the fill window.
//  * steady loop uses smooth depth-2 rolling refill: each tap's slot is
//    rotated and refilled right after its last consumer FMA, keeping ~10
//    loads in flight continuously (R12 finding).
//  * __ldcs on filters / __stcs on output: the 368MB+44MB streams are
//    evict-first so the 2.8MB x stays L2-resident.
//   x:       (4, 3, 180, 320) f32
//   filters: (4, 25, 16, 180, 320) f32
//   out:     (4, 48, 180, 320) f32
//   out[n, c*16+u, h, w] = sum_p x_pad[n, c, h+p/5-2, w+p%5-2] * filters[n, p, u, h, w]

#define NN 4
#define CC 3
#define HH 180
#define WW 320
#define UU 16
#define KH 5
#define KW 5
#define PP (KH*KW)
#define TILE_W 64
#define SROW 68                 // TILE_W + 4 halo
#define XELEMS (CC * KH * SROW) // 1020 smem elements

__global__ void __launch_bounds__(256, 4)
duf_kernel(const float* __restrict__ x,
           const float* __restrict__ filters,
           float* __restrict__ out) {
    // Block: one (n, h, w-tile of 64). 256 threads = 16 u-values x 16 w-quads.
    __shared__ float sx[CC][KH][SROW];  // 4080 B

    const int wq = threadIdx.x & 15;
    const int u  = threadIdx.x >> 4;
    const int wb = blockIdx.x * TILE_W;
    const int h  = blockIdx.y;
    const int n  = blockIdx.z;

    const int w0 = wb + wq * 4;
    const float* fp = filters + ((((size_t)n * PP) * UU + u) * HH + h) * WW + w0;
    const size_t PS = (size_t)UU * HH * WW;  // p-plane stride (elements)

    // ---- (1) x-tile loads FIRST (L2 hits ahead of filter DRAM misses)
    float xv[4];
    #pragma unroll
    for (int k = 0; k < 4; ++k) {
        const int e = threadIdx.x + k * 256;
        float v = 0.0f;
        if (e < XELEMS) {
            const int pos = e % SROW;
            const int t   = e / SROW;
            const int i   = t % KH;
            const int c   = t / KH;
            const int col = wb + pos - 2;
            const int row = h + i - 2;
            if ((unsigned)col < WW && (unsigned)row < HH)
                v = __ldg(&x[((n * CC + c) * HH + row) * WW + col]);
        }
        xv[k] = v;
    }

    // ---- (2) hoist filter rows 0 AND 1: 10 LDG.128 in flight during fill
    float4 cur[KW], nxt[KW];
    #pragma unroll
    for (int j = 0; j < KW; ++j)
        cur[j] = __ldcs(reinterpret_cast<const float4*>(fp + (size_t)j * PS));
    #pragma unroll
    for (int j = 0; j < KW; ++j)
        nxt[j] = __ldcs(reinterpret_cast<const float4*>(fp + (size_t)(KW + j) * PS));

    // ---- (3) store x tile + barrier (waits only on the x loads)
    float* sflat = &sx[0][0][0];
    #pragma unroll
    for (int k = 0; k < 4; ++k) {
        const int e = threadIdx.x + k * 256;
        if (e < XELEMS) sflat[e] = xv[k];
    }
    __syncthreads();

    float4 acc[CC];
    #pragma unroll
    for (int c = 0; c < CC; ++c) acc[c] = make_float4(0.f, 0.f, 0.f, 0.f);

    // ---- (4) steady loop, smooth depth-2 rolling refill
    #pragma unroll
    for (int i = 0; i < KH; ++i) {
        #pragma unroll
        for (int c = 0; c < CC; ++c) {
            const float4 a = *reinterpret_cast<const float4*>(&sx[c][i][wq * 4]);
            const float4 b = *reinterpret_cast<const float4*>(&sx[c][i][wq * 4 + 4]);
            const float pr[8] = {a.x, a.y, a.z, a.w, b.x, b.y, b.z, b.w};
            #pragma unroll
            for (int j = 0; j < KW; ++j) {
                acc[c].x = fmaf(pr[j + 0], cur[j].x, acc[c].x);
                acc[c].y = fmaf(pr[j + 1], cur[j].y, acc[c].y);
                acc[c].z = fmaf(pr[j + 2], cur[j].z, acc[c].z);
                acc[c].w = fmaf(pr[j + 3], cur[j].w, acc[c].w);
                // after the LAST channel consumes cur[j], rotate + refill it
                if (c == CC - 1 && i < KH - 1) {
                    cur[j] = nxt[j];
                    if (i < KH - 2)
                        nxt[j] = __ldcs(reinterpret_cast<const float4*>(
                            fp + (size_t)((i + 2) * KW + j) * PS));
                }
            }
        }
    }

    // ---- store: out[n, c*16+u, h, w0..w0+3] ----
    #pragma unroll
    for (int c = 0; c < CC; ++c) {
        float4* optr = reinterpret_cast<float4*>(
            out + ((((size_t)n * (CC * UU)) + c * UU + u) * HH + h) * WW + w0);
        __stcs(optr, acc[c]);
    }
}

extern "C" void kernel_launch(void* const* d_in, const int* in_sizes, int n_in,
                              void* d_out, int out_size) {
    const float* x       = (const float*)d_in[0];
    const float* filters = (const float*)d_in[1];
    float* out           = (float*)d_out;

    dim3 grid(WW / TILE_W, HH, NN);  // (5, 180, 4) = 3600 blocks
    dim3 block(256);
    duf_kernel<<<grid, block>>>(x, filters, out);
}